// round 2
// baseline (speedup 1.0000x reference)
#include <cuda_runtime.h>
#include <math.h>

#define SS 8192
#define DD 1024
#define HH 16
#define HDIM 64

// Scratch (static device arrays -- no allocation in kernel_launch)
__device__ float g_Q[SS * DD];
__device__ float g_K[SS * DD];
__device__ float g_V[SS * DD];
__device__ float g_O[SS * DD];

// ---------------------------------------------------------------------------
// SGEMM: C[m,n] = sum_k A[m,k] * W[n,k] + bias[n]
// A: MxK row-major, W: NxK row-major (i.e. C = A * W^T + b)
// Tiles: 128x128 per block, K-step 8, 256 threads, 8x8 per thread.
// ---------------------------------------------------------------------------
__global__ __launch_bounds__(256, 2)
void gemm128(const float* __restrict__ A, const float* __restrict__ W,
             const float* __restrict__ bias, float* __restrict__ C,
             int M, int N, int K) {
    __shared__ float sA[8][128];
    __shared__ float sB[8][128];

    const int tid = threadIdx.x;
    const int m0 = blockIdx.y * 128;
    const int n0 = blockIdx.x * 128;

    const int lr = tid >> 1;          // 0..127 : row within tile for loads
    const int lc = (tid & 1) * 4;     // 0 or 4 : col group for loads
    const int ty = tid >> 4;          // 0..15
    const int tx = tid & 15;          // 0..15

    float acc[8][8];
#pragma unroll
    for (int i = 0; i < 8; i++)
#pragma unroll
        for (int j = 0; j < 8; j++) acc[i][j] = 0.f;

    for (int k0 = 0; k0 < K; k0 += 8) {
        float4 a = *(const float4*)&A[(size_t)(m0 + lr) * K + k0 + lc];
        float4 b = *(const float4*)&W[(size_t)(n0 + lr) * K + k0 + lc];
        sA[lc + 0][lr] = a.x; sA[lc + 1][lr] = a.y;
        sA[lc + 2][lr] = a.z; sA[lc + 3][lr] = a.w;
        sB[lc + 0][lr] = b.x; sB[lc + 1][lr] = b.y;
        sB[lc + 2][lr] = b.z; sB[lc + 3][lr] = b.w;
        __syncthreads();

#pragma unroll
        for (int kk = 0; kk < 8; kk++) {
            float4 ra0 = *(const float4*)&sA[kk][ty * 8];
            float4 ra1 = *(const float4*)&sA[kk][ty * 8 + 4];
            float4 rb0 = *(const float4*)&sB[kk][tx * 8];
            float4 rb1 = *(const float4*)&sB[kk][tx * 8 + 4];
            float ra[8] = {ra0.x, ra0.y, ra0.z, ra0.w, ra1.x, ra1.y, ra1.z, ra1.w};
            float rb[8] = {rb0.x, rb0.y, rb0.z, rb0.w, rb1.x, rb1.y, rb1.z, rb1.w};
#pragma unroll
            for (int i = 0; i < 8; i++)
#pragma unroll
                for (int j = 0; j < 8; j++) acc[i][j] += ra[i] * rb[j];
        }
        __syncthreads();
    }

#pragma unroll
    for (int i = 0; i < 8; i++) {
        const int m = m0 + ty * 8 + i;
#pragma unroll
        for (int j = 0; j < 8; j += 4) {
            const int n = n0 + tx * 8 + j;
            float4 o;
            o.x = acc[i][j + 0] + bias[n + 0];
            o.y = acc[i][j + 1] + bias[n + 1];
            o.z = acc[i][j + 2] + bias[n + 2];
            o.w = acc[i][j + 3] + bias[n + 3];
            *(float4*)&C[(size_t)m * N + n] = o;
        }
    }
}

// ---------------------------------------------------------------------------
// Sliding-window flash attention (fp32, online softmax).
// Block = 128 queries x 1 head. Key tiles of 64 covering [qs-512, qs+127+512].
// Thread layout: kg = tid&7 (8 key-groups / dim-groups), qg = tid>>3 (32 q-groups of 4).
// Score phase:   thread -> 4 queries x 8 keys (keys kg, kg+8, ..., kg+56)
// PV phase:      thread -> 4 queries x 8 dims (dims kg*8 .. kg*8+7)
// Epilogue applies the overlap-add blend weight: 1 everywhere except
// p in [S-128, S): w = 1 + (p - (S-128))/127.
// ---------------------------------------------------------------------------
#define QTILE 128
#define KTILE 64
#define LDPAD 68   // row stride in floats (bank-stagger, 16B aligned)

__global__ __launch_bounds__(256, 2)
void attn_kernel(const float* __restrict__ Qg, const float* __restrict__ Kg,
                 const float* __restrict__ Vg, float* __restrict__ Og) {
    extern __shared__ float sm[];
    float* sQ = sm;                       // 128*68
    float* sK = sQ + QTILE * LDPAD;       // 64*68
    float* sV = sK + KTILE * LDPAD;       // 64*68
    float* sP = sV + KTILE * LDPAD;       // 128*68

    const int tid = threadIdx.x;
    const int qs = blockIdx.x * QTILE;
    const int hoff = blockIdx.y * HDIM;

    const int kg = tid & 7;
    const int qg = tid >> 3;
    const int q0 = qg * 4;

    // ---- load Q tile [128][64] ----
    {
        const int r = tid >> 1;
        const int half = (tid & 1) * 32;
        const float* src = Qg + (size_t)(qs + r) * DD + hoff + half;
        float* dst = sQ + r * LDPAD + half;
#pragma unroll
        for (int j = 0; j < 8; j++)
            *(float4*)(dst + 4 * j) = *(const float4*)(src + 4 * j);
    }

    float m[4], l[4], o[4][8];
#pragma unroll
    for (int i = 0; i < 4; i++) {
        m[i] = -1e30f; l[i] = 0.f;
#pragma unroll
        for (int d = 0; d < 8; d++) o[i][d] = 0.f;
    }
    __syncthreads();

    for (int t = 0; t < 18; t++) {
        const int kt = qs - 512 + 64 * t;
        if (kt >= SS || kt + KTILE <= 0) continue;

        // ---- load K,V tile [64][64] (zero-fill OOB rows) ----
        {
            const int r = tid >> 2;           // 0..63
            const int cw = (tid & 3) * 16;    // 0,16,32,48
            const int kabs = kt + r;
            float* kdst = sK + r * LDPAD + cw;
            float* vdst = sV + r * LDPAD + cw;
            if (kabs >= 0 && kabs < SS) {
                const float* kp = Kg + (size_t)kabs * DD + hoff + cw;
                const float* vp = Vg + (size_t)kabs * DD + hoff + cw;
#pragma unroll
                for (int j = 0; j < 4; j++) {
                    *(float4*)(kdst + 4 * j) = *(const float4*)(kp + 4 * j);
                    *(float4*)(vdst + 4 * j) = *(const float4*)(vp + 4 * j);
                }
            } else {
                const float4 z = make_float4(0.f, 0.f, 0.f, 0.f);
#pragma unroll
                for (int j = 0; j < 4; j++) {
                    *(float4*)(kdst + 4 * j) = z;
                    *(float4*)(vdst + 4 * j) = z;
                }
            }
        }
        __syncthreads();

        // ---- scores: acc[i][j] = q(q0+i) . k(kg+8j) ----
        float acc[4][8];
#pragma unroll
        for (int i = 0; i < 4; i++)
#pragma unroll
            for (int j = 0; j < 8; j++) acc[i][j] = 0.f;

#pragma unroll
        for (int d4 = 0; d4 < HDIM; d4 += 4) {
            float4 qv[4];
#pragma unroll
            for (int i = 0; i < 4; i++)
                qv[i] = *(const float4*)&sQ[(q0 + i) * LDPAD + d4];
#pragma unroll
            for (int j = 0; j < 8; j++) {
                float4 kv = *(const float4*)&sK[(kg + 8 * j) * LDPAD + d4];
#pragma unroll
                for (int i = 0; i < 4; i++) {
                    acc[i][j] += qv[i].x * kv.x;
                    acc[i][j] += qv[i].y * kv.y;
                    acc[i][j] += qv[i].z * kv.z;
                    acc[i][j] += qv[i].w * kv.w;
                }
            }
        }

        // ---- mask + online softmax update ----
#pragma unroll
        for (int i = 0; i < 4; i++) {
            const int qabs = qs + q0 + i;
            float s[8];
            float rmax = -1e30f;
#pragma unroll
            for (int j = 0; j < 8; j++) {
                const int kabs = kt + kg + 8 * j;
                const bool ok = (kabs >= 0) & (kabs < SS) &
                                (kabs >= qabs - 512) & (kabs < qabs + 512);
                s[j] = ok ? acc[i][j] * 0.125f : -1e30f;
                rmax = fmaxf(rmax, s[j]);
            }
            rmax = fmaxf(rmax, __shfl_xor_sync(0xffffffffu, rmax, 1));
            rmax = fmaxf(rmax, __shfl_xor_sync(0xffffffffu, rmax, 2));
            rmax = fmaxf(rmax, __shfl_xor_sync(0xffffffffu, rmax, 4));
            const float mn = fmaxf(m[i], rmax);
            float rsum = 0.f;
#pragma unroll
            for (int j = 0; j < 8; j++) {
                const float p = (s[j] > -5e29f) ? __expf(s[j] - mn) : 0.f;
                rsum += p;
                sP[(q0 + i) * LDPAD + kg + 8 * j] = p;
            }
            rsum += __shfl_xor_sync(0xffffffffu, rsum, 1);
            rsum += __shfl_xor_sync(0xffffffffu, rsum, 2);
            rsum += __shfl_xor_sync(0xffffffffu, rsum, 4);
            const float alpha = __expf(m[i] - mn);
            l[i] = l[i] * alpha + rsum;
            m[i] = mn;
#pragma unroll
            for (int d = 0; d < 8; d++) o[i][d] *= alpha;
        }
        __syncthreads();

        // ---- PV: o[i][d] += sum_k p[q0+i][k] * V[k][kg*8+d] ----
#pragma unroll
        for (int k4 = 0; k4 < KTILE; k4 += 4) {
            float pk[4][4];
#pragma unroll
            for (int i = 0; i < 4; i++) {
                float4 pv = *(const float4*)&sP[(q0 + i) * LDPAD + k4];
                pk[i][0] = pv.x; pk[i][1] = pv.y; pk[i][2] = pv.z; pk[i][3] = pv.w;
            }
#pragma unroll
            for (int kk = 0; kk < 4; kk++) {
                float4 va = *(const float4*)&sV[(k4 + kk) * LDPAD + kg * 8];
                float4 vb = *(const float4*)&sV[(k4 + kk) * LDPAD + kg * 8 + 4];
#pragma unroll
                for (int i = 0; i < 4; i++) {
                    o[i][0] += pk[i][kk] * va.x;
                    o[i][1] += pk[i][kk] * va.y;
                    o[i][2] += pk[i][kk] * va.z;
                    o[i][3] += pk[i][kk] * va.w;
                    o[i][4] += pk[i][kk] * vb.x;
                    o[i][5] += pk[i][kk] * vb.y;
                    o[i][6] += pk[i][kk] * vb.z;
                    o[i][7] += pk[i][kk] * vb.w;
                }
            }
        }
        __syncthreads();
    }

    // ---- epilogue: normalize, apply overlap-add blend weight, store ----
#pragma unroll
    for (int i = 0; i < 4; i++) {
        const int qabs = qs + q0 + i;
        // Total chunk blend weight: 1 except [S-128, S): 1 + (p-(S-128))/127
        float w = 1.f;
        if (qabs >= SS - 128) w = 1.f + (float)(qabs - (SS - 128)) * (1.f / 127.f);
        const float sc = w / l[i];
        float* dst = Og + (size_t)qabs * DD + hoff + kg * 8;
        float4 oa, ob;
        oa.x = o[i][0] * sc; oa.y = o[i][1] * sc; oa.z = o[i][2] * sc; oa.w = o[i][3] * sc;
        ob.x = o[i][4] * sc; ob.y = o[i][5] * sc; ob.z = o[i][6] * sc; ob.w = o[i][7] * sc;
        *(float4*)(dst + 0) = oa;
        *(float4*)(dst + 4) = ob;
    }
}

// ---------------------------------------------------------------------------
extern "C" void kernel_launch(void* const* d_in, const int* in_sizes, int n_in,
                              void* d_out, int out_size) {
    // Bind inputs by SIZE, not position, so either metadata ordering works:
    //   x: 8192*1024 = 8388608 elems
    //   W*: 1024*1024 = 1048576 elems  (relative order: Wq, Wk, Wv, Wo)
    //   b*: 1024 elems                 (relative order: bq, bk, bv, bo)
    const float* x = nullptr;
    const float* Wm[4] = {nullptr, nullptr, nullptr, nullptr};
    const float* bv_[4] = {nullptr, nullptr, nullptr, nullptr};
    int nw = 0, nb = 0;
    for (int i = 0; i < n_in; i++) {
        const float* p = (const float*)d_in[i];
        if (in_sizes[i] == SS * DD) {
            x = p;
        } else if (in_sizes[i] == DD * DD) {
            if (nw < 4) Wm[nw++] = p;
        } else if (in_sizes[i] == DD) {
            if (nb < 4) bv_[nb++] = p;
        }
    }
    const float *Wq = Wm[0], *Wk = Wm[1], *Wv = Wm[2], *Wo = Wm[3];
    const float *bq = bv_[0], *bk = bv_[1], *bvv = bv_[2], *bo = bv_[3];
    float* out = (float*)d_out;

    float *Qp, *Kp, *Vp, *Op;
    cudaGetSymbolAddress((void**)&Qp, g_Q);
    cudaGetSymbolAddress((void**)&Kp, g_K);
    cudaGetSymbolAddress((void**)&Vp, g_V);
    cudaGetSymbolAddress((void**)&Op, g_O);

    dim3 ggrid(DD / 128, SS / 128);   // (8, 64)
    gemm128<<<ggrid, 256>>>(x, Wq, bq, Qp, SS, DD, DD);
    gemm128<<<ggrid, 256>>>(x, Wk, bk, Kp, SS, DD, DD);
    gemm128<<<ggrid, 256>>>(x, Wv, bvv, Vp, SS, DD, DD);

    const size_t shmem = (size_t)(QTILE + KTILE + KTILE + QTILE) * LDPAD * sizeof(float);
    cudaFuncSetAttribute(attn_kernel, cudaFuncAttributeMaxDynamicSharedMemorySize,
                         (int)shmem);
    attn_kernel<<<dim3(SS / QTILE, HH), 256, shmem>>>(Qp, Kp, Vp, Op);

    gemm128<<<ggrid, 256>>>(Op, Wo, bo, out, SS, DD, DD);
}

// round 4
// speedup vs baseline: 1.2252x; 1.2252x over previous
#include <cuda_runtime.h>
#include <cuda_bf16.h>
#include <stdint.h>
#include <math.h>

#define SS 8192
#define DD 1024
#define HH 16
#define HDIM 64

// Scratch (static device arrays -- no allocation in kernel_launch)
__device__ float g_Q[SS * DD];
__device__ float g_K[SS * DD];
__device__ float g_V[SS * DD];
__device__ float g_O[SS * DD];

// ===========================================================================
// PTX helpers (baseline ISA only: ldmatrix + mma.sync, sm_80+)
// ===========================================================================
__device__ __forceinline__ uint32_t smem_u32(const void* p) {
    uint32_t a;
    asm("{ .reg .u64 t; cvta.to.shared.u64 t, %1; cvt.u32.u64 %0, t; }"
        : "=r"(a) : "l"(p));
    return a;
}

#define LDSM_X4(r0, r1, r2, r3, addr)                                       \
    asm volatile(                                                           \
        "ldmatrix.sync.aligned.m8n8.x4.shared.b16 {%0, %1, %2, %3}, [%4];"  \
        : "=r"(r0), "=r"(r1), "=r"(r2), "=r"(r3) : "r"(addr))

#define MMA16816(d, a, b)                                                   \
    asm volatile(                                                           \
        "mma.sync.aligned.m16n8k16.row.col.f32.bf16.bf16.f32 "              \
        "{%0, %1, %2, %3}, {%4, %5, %6, %7}, {%8, %9}, {%0, %1, %2, %3};"   \
        : "+f"((d)[0]), "+f"((d)[1]), "+f"((d)[2]), "+f"((d)[3])            \
        : "r"((a)[0]), "r"((a)[1]), "r"((a)[2]), "r"((a)[3]),               \
          "r"((b)[0]), "r"((b)[1]))

// ===========================================================================
// mma.sync GEMM with bf16x3 emulated-fp32:
//   C[m,n] = sum_k A[m,k] * W[n,k] + bias[n]
// A: 8192x1024 row-major, W: 1024x1024 row-major (k contiguous = B col-major).
// CTA tile 128x128, K-chunk 64, 256 threads (8 warps, each 32m x 64n).
// Products per step: Ahi*Bhi + Ahi*Blo + Alo*Bhi  (fp32 accum).
// ===========================================================================
#define OFF_BIAS 0
#define OFF_AH   1024
#define OFF_AL   (1024 + 16384)
#define OFF_BH   (1024 + 32768)
#define OFF_BL   (1024 + 49152)
#define GEMM_SMEM (1024 + 65536)

#define SWZ(o) ((o) ^ (((o) >> 3) & 0x70))

__device__ __forceinline__ void cvt_split(float4 v, uint2& hi, uint2& lo) {
    __nv_bfloat16 hx = __float2bfloat16(v.x);
    __nv_bfloat16 hy = __float2bfloat16(v.y);
    __nv_bfloat16 hz = __float2bfloat16(v.z);
    __nv_bfloat16 hw = __float2bfloat16(v.w);
    __nv_bfloat16 lx = __float2bfloat16(v.x - __bfloat162float(hx));
    __nv_bfloat16 ly = __float2bfloat16(v.y - __bfloat162float(hy));
    __nv_bfloat16 lz = __float2bfloat16(v.z - __bfloat162float(hz));
    __nv_bfloat16 lw = __float2bfloat16(v.w - __bfloat162float(hw));
    __nv_bfloat162 h01, h23, l01, l23;
    h01.x = hx; h01.y = hy; h23.x = hz; h23.y = hw;
    l01.x = lx; l01.y = ly; l23.x = lz; l23.y = lw;
    hi.x = *(uint32_t*)&h01; hi.y = *(uint32_t*)&h23;
    lo.x = *(uint32_t*)&l01; lo.y = *(uint32_t*)&l23;
}

__global__ __launch_bounds__(256)
void gemm_mma(const float* __restrict__ A, const float* __restrict__ W,
              const float* __restrict__ bias, float* __restrict__ C) {
    extern __shared__ char sm[];
    const uint32_t sbase = smem_u32(sm);
    float* sbias = (float*)(sm + OFF_BIAS);

    const int tid = threadIdx.x;
    const int wid = tid >> 5, lane = tid & 31;
    const int n0 = blockIdx.x * 128, m0 = blockIdx.y * 128;

    if (tid < 128) sbias[tid] = bias[n0 + tid];

    const int wm = (wid & 3) * 32;    // warp m-offset in tile
    const int wn = (wid >> 2) * 64;   // warp n-offset in tile

    float acc[2][8][4];
#pragma unroll
    for (int mt = 0; mt < 2; mt++)
#pragma unroll
        for (int nt = 0; nt < 8; nt++)
#pragma unroll
            for (int e = 0; e < 4; e++) acc[mt][nt][e] = 0.f;

    // conversion-load assignment: thread -> half row (32 floats)
    const int cr = tid >> 1;
    const int hc = (tid & 1) * 32;
    const float* pa = A + (size_t)(m0 + cr) * DD + hc;
    const float* pb = W + (size_t)(n0 + cr) * DD + hc;

    // ldmatrix lane address components
    const int local = lane & 7, sel = lane >> 3;

    for (int c = 0; c < DD / 64; c++) {
        // ---- stage chunk: fp32 -> bf16 hi/lo, swizzled smem ----
#pragma unroll
        for (int j = 0; j < 8; j++) {
            float4 av = *(const float4*)(pa + c * 64 + 4 * j);
            float4 bv = *(const float4*)(pb + c * 64 + 4 * j);
            uint32_t off = SWZ((uint32_t)(cr * 128 + (hc + 4 * j) * 2));
            uint2 ahi, alo, bhi, blo;
            cvt_split(av, ahi, alo);
            cvt_split(bv, bhi, blo);
            *(uint2*)(sm + OFF_AH + off) = ahi;
            *(uint2*)(sm + OFF_AL + off) = alo;
            *(uint2*)(sm + OFF_BH + off) = bhi;
            *(uint2*)(sm + OFF_BL + off) = blo;
        }
        __syncthreads();

#pragma unroll
        for (int kk = 0; kk < 64; kk += 16) {
            // ---- A fragments (m16 x k16 per ldmatrix.x4) ----
            uint32_t ah[2][4], al[2][4];
#pragma unroll
            for (int mt = 0; mt < 2; mt++) {
                const int row = wm + mt * 16 + local + (sel & 1) * 8;
                const int kb = kk + (sel >> 1) * 8;
                const uint32_t off = SWZ((uint32_t)(row * 128 + kb * 2));
                LDSM_X4(ah[mt][0], ah[mt][1], ah[mt][2], ah[mt][3],
                        sbase + OFF_AH + off);
                LDSM_X4(al[mt][0], al[mt][1], al[mt][2], al[mt][3],
                        sbase + OFF_AL + off);
            }
            // ---- B fragments (2 n-tiles per ldmatrix.x4) ----
            uint32_t bh[8][2], bl[8][2];
#pragma unroll
            for (int np = 0; np < 4; np++) {
                const int row = wn + np * 16 + (sel >> 1) * 8 + local;
                const int kb = kk + (sel & 1) * 8;
                const uint32_t off = SWZ((uint32_t)(row * 128 + kb * 2));
                uint32_t t0, t1, t2, t3;
                LDSM_X4(t0, t1, t2, t3, sbase + OFF_BH + off);
                bh[2 * np][0] = t0; bh[2 * np][1] = t1;
                bh[2 * np + 1][0] = t2; bh[2 * np + 1][1] = t3;
                LDSM_X4(t0, t1, t2, t3, sbase + OFF_BL + off);
                bl[2 * np][0] = t0; bl[2 * np][1] = t1;
                bl[2 * np + 1][0] = t2; bl[2 * np + 1][1] = t3;
            }
            // ---- 3-product MMAs ----
#pragma unroll
            for (int mt = 0; mt < 2; mt++)
#pragma unroll
                for (int nt = 0; nt < 8; nt++) {
                    MMA16816(acc[mt][nt], ah[mt], bh[nt]);
                    MMA16816(acc[mt][nt], ah[mt], bl[nt]);
                    MMA16816(acc[mt][nt], al[mt], bh[nt]);
                }
        }
        __syncthreads();
    }

    // ---- epilogue: acc + bias -> C ----
    const int er = lane >> 2;
    const int ec = (lane & 3) * 2;
#pragma unroll
    for (int mt = 0; mt < 2; mt++) {
#pragma unroll
        for (int nt = 0; nt < 8; nt++) {
            const int ct = wn + nt * 8 + ec;
            const int row0 = m0 + wm + mt * 16 + er;
            float2 v0, v1;
            v0.x = acc[mt][nt][0] + sbias[ct];
            v0.y = acc[mt][nt][1] + sbias[ct + 1];
            v1.x = acc[mt][nt][2] + sbias[ct];
            v1.y = acc[mt][nt][3] + sbias[ct + 1];
            *(float2*)&C[(size_t)row0 * DD + n0 + ct] = v0;
            *(float2*)&C[(size_t)(row0 + 8) * DD + n0 + ct] = v1;
        }
    }
}

// ===========================================================================
// Sliding-window flash attention (fp32, online softmax) -- unchanged (passing)
// ===========================================================================
#define QTILE 128
#define KTILE 64
#define LDPAD 68

__global__ __launch_bounds__(256, 2)
void attn_kernel(const float* __restrict__ Qg, const float* __restrict__ Kg,
                 const float* __restrict__ Vg, float* __restrict__ Og) {
    extern __shared__ float smf[];
    float* sQ = smf;
    float* sK = sQ + QTILE * LDPAD;
    float* sV = sK + KTILE * LDPAD;
    float* sP = sV + KTILE * LDPAD;

    const int tid = threadIdx.x;
    const int qs = blockIdx.x * QTILE;
    const int hoff = blockIdx.y * HDIM;

    const int kg = tid & 7;
    const int qg = tid >> 3;
    const int q0 = qg * 4;

    {
        const int r = tid >> 1;
        const int half = (tid & 1) * 32;
        const float* src = Qg + (size_t)(qs + r) * DD + hoff + half;
        float* dst = sQ + r * LDPAD + half;
#pragma unroll
        for (int j = 0; j < 8; j++)
            *(float4*)(dst + 4 * j) = *(const float4*)(src + 4 * j);
    }

    float m[4], l[4], o[4][8];
#pragma unroll
    for (int i = 0; i < 4; i++) {
        m[i] = -1e30f; l[i] = 0.f;
#pragma unroll
        for (int d = 0; d < 8; d++) o[i][d] = 0.f;
    }
    __syncthreads();

    for (int t = 0; t < 18; t++) {
        const int kt = qs - 512 + 64 * t;
        if (kt >= SS || kt + KTILE <= 0) continue;

        {
            const int r = tid >> 2;
            const int cw = (tid & 3) * 16;
            const int kabs = kt + r;
            float* kdst = sK + r * LDPAD + cw;
            float* vdst = sV + r * LDPAD + cw;
            if (kabs >= 0 && kabs < SS) {
                const float* kp = Kg + (size_t)kabs * DD + hoff + cw;
                const float* vp = Vg + (size_t)kabs * DD + hoff + cw;
#pragma unroll
                for (int j = 0; j < 4; j++) {
                    *(float4*)(kdst + 4 * j) = *(const float4*)(kp + 4 * j);
                    *(float4*)(vdst + 4 * j) = *(const float4*)(vp + 4 * j);
                }
            } else {
                const float4 z = make_float4(0.f, 0.f, 0.f, 0.f);
#pragma unroll
                for (int j = 0; j < 4; j++) {
                    *(float4*)(kdst + 4 * j) = z;
                    *(float4*)(vdst + 4 * j) = z;
                }
            }
        }
        __syncthreads();

        float acc[4][8];
#pragma unroll
        for (int i = 0; i < 4; i++)
#pragma unroll
            for (int j = 0; j < 8; j++) acc[i][j] = 0.f;

#pragma unroll
        for (int d4 = 0; d4 < HDIM; d4 += 4) {
            float4 qv[4];
#pragma unroll
            for (int i = 0; i < 4; i++)
                qv[i] = *(const float4*)&sQ[(q0 + i) * LDPAD + d4];
#pragma unroll
            for (int j = 0; j < 8; j++) {
                float4 kv = *(const float4*)&sK[(kg + 8 * j) * LDPAD + d4];
#pragma unroll
                for (int i = 0; i < 4; i++) {
                    acc[i][j] += qv[i].x * kv.x;
                    acc[i][j] += qv[i].y * kv.y;
                    acc[i][j] += qv[i].z * kv.z;
                    acc[i][j] += qv[i].w * kv.w;
                }
            }
        }

#pragma unroll
        for (int i = 0; i < 4; i++) {
            const int qabs = qs + q0 + i;
            float s[8];
            float rmax = -1e30f;
#pragma unroll
            for (int j = 0; j < 8; j++) {
                const int kabs = kt + kg + 8 * j;
                const bool ok = (kabs >= 0) & (kabs < SS) &
                                (kabs >= qabs - 512) & (kabs < qabs + 512);
                s[j] = ok ? acc[i][j] * 0.125f : -1e30f;
                rmax = fmaxf(rmax, s[j]);
            }
            rmax = fmaxf(rmax, __shfl_xor_sync(0xffffffffu, rmax, 1));
            rmax = fmaxf(rmax, __shfl_xor_sync(0xffffffffu, rmax, 2));
            rmax = fmaxf(rmax, __shfl_xor_sync(0xffffffffu, rmax, 4));
            const float mn = fmaxf(m[i], rmax);
            float rsum = 0.f;
#pragma unroll
            for (int j = 0; j < 8; j++) {
                const float p = (s[j] > -5e29f) ? __expf(s[j] - mn) : 0.f;
                rsum += p;
                sP[(q0 + i) * LDPAD + kg + 8 * j] = p;
            }
            rsum += __shfl_xor_sync(0xffffffffu, rsum, 1);
            rsum += __shfl_xor_sync(0xffffffffu, rsum, 2);
            rsum += __shfl_xor_sync(0xffffffffu, rsum, 4);
            const float alpha = __expf(m[i] - mn);
            l[i] = l[i] * alpha + rsum;
            m[i] = mn;
#pragma unroll
            for (int d = 0; d < 8; d++) o[i][d] *= alpha;
        }
        __syncthreads();

#pragma unroll
        for (int k4 = 0; k4 < KTILE; k4 += 4) {
            float pk[4][4];
#pragma unroll
            for (int i = 0; i < 4; i++) {
                float4 pv = *(const float4*)&sP[(q0 + i) * LDPAD + k4];
                pk[i][0] = pv.x; pk[i][1] = pv.y; pk[i][2] = pv.z; pk[i][3] = pv.w;
            }
#pragma unroll
            for (int kk = 0; kk < 4; kk++) {
                float4 va = *(const float4*)&sV[(k4 + kk) * LDPAD + kg * 8];
                float4 vb = *(const float4*)&sV[(k4 + kk) * LDPAD + kg * 8 + 4];
#pragma unroll
                for (int i = 0; i < 4; i++) {
                    o[i][0] += pk[i][kk] * va.x;
                    o[i][1] += pk[i][kk] * va.y;
                    o[i][2] += pk[i][kk] * va.z;
                    o[i][3] += pk[i][kk] * va.w;
                    o[i][4] += pk[i][kk] * vb.x;
                    o[i][5] += pk[i][kk] * vb.y;
                    o[i][6] += pk[i][kk] * vb.z;
                    o[i][7] += pk[i][kk] * vb.w;
                }
            }
        }
        __syncthreads();
    }

#pragma unroll
    for (int i = 0; i < 4; i++) {
        const int qabs = qs + q0 + i;
        float w = 1.f;
        if (qabs >= SS - 128) w = 1.f + (float)(qabs - (SS - 128)) * (1.f / 127.f);
        const float sc = w / l[i];
        float* dst = Og + (size_t)qabs * DD + hoff + kg * 8;
        float4 oa, ob;
        oa.x = o[i][0] * sc; oa.y = o[i][1] * sc; oa.z = o[i][2] * sc; oa.w = o[i][3] * sc;
        ob.x = o[i][4] * sc; ob.y = o[i][5] * sc; ob.z = o[i][6] * sc; ob.w = o[i][7] * sc;
        *(float4*)(dst + 0) = oa;
        *(float4*)(dst + 4) = ob;
    }
}

// ===========================================================================
extern "C" void kernel_launch(void* const* d_in, const int* in_sizes, int n_in,
                              void* d_out, int out_size) {
    // Bind inputs by size (robust to metadata ordering):
    const float* x = nullptr;
    const float* Wm[4] = {nullptr, nullptr, nullptr, nullptr};
    const float* bm[4] = {nullptr, nullptr, nullptr, nullptr};
    int nw = 0, nb = 0;
    for (int i = 0; i < n_in; i++) {
        const float* p = (const float*)d_in[i];
        if (in_sizes[i] == SS * DD) x = p;
        else if (in_sizes[i] == DD * DD) { if (nw < 4) Wm[nw++] = p; }
        else if (in_sizes[i] == DD) { if (nb < 4) bm[nb++] = p; }
    }
    const float *Wq = Wm[0], *Wk = Wm[1], *Wv = Wm[2], *Wo = Wm[3];
    const float *bq = bm[0], *bk = bm[1], *bvv = bm[2], *bo = bm[3];
    float* out = (float*)d_out;

    float *Qp, *Kp, *Vp, *Op;
    cudaGetSymbolAddress((void**)&Qp, g_Q);
    cudaGetSymbolAddress((void**)&Kp, g_K);
    cudaGetSymbolAddress((void**)&Vp, g_V);
    cudaGetSymbolAddress((void**)&Op, g_O);

    cudaFuncSetAttribute(gemm_mma, cudaFuncAttributeMaxDynamicSharedMemorySize,
                         GEMM_SMEM);

    dim3 ggrid(DD / 128, SS / 128);   // (8, 64)
    gemm_mma<<<ggrid, 256, GEMM_SMEM>>>(x, Wq, bq, Qp);
    gemm_mma<<<ggrid, 256, GEMM_SMEM>>>(x, Wk, bk, Kp);
    gemm_mma<<<ggrid, 256, GEMM_SMEM>>>(x, Wv, bvv, Vp);

    const size_t shmem = (size_t)(QTILE + KTILE + KTILE + QTILE) * LDPAD * sizeof(float);
    cudaFuncSetAttribute(attn_kernel, cudaFuncAttributeMaxDynamicSharedMemorySize,
                         (int)shmem);
    attn_kernel<<<dim3(SS / QTILE, HH), 256, shmem>>>(Qp, Kp, Vp, Op);

    gemm_mma<<<ggrid, 256, GEMM_SMEM>>>(Op, Wo, bo, out);
}